// round 17
// baseline (speedup 1.0000x reference)
#include <cuda_runtime.h>
#include <cuda_bf16.h>
#include <cuda_fp16.h>
#include <cstdint>
#include <cstddef>

#define TPB 224
#define NWARP 7
#define EPC 224          // elements per CTA (7 warps x 32)

// ---------------- helpers ----------------
__device__ __forceinline__ uint32_t f16x2_of(float lo, float hi) {
    uint32_t r; asm("cvt.rn.f16x2.f32 %0, %1, %2;" : "=r"(r) : "f"(hi), "f"(lo)); return r;
}
__device__ __forceinline__ uint32_t tanh2(uint32_t x) {
    uint32_t y; asm("tanh.approx.f16x2 %0, %1;" : "=r"(y) : "r"(x)); return y;
}
__device__ __forceinline__ float softplus_(float x) {
    return fmaxf(x, 0.0f) + __logf(1.0f + __expf(-fabsf(x)));
}
__device__ __forceinline__ void mma_f16(float* c, const uint32_t* a, uint32_t b0, uint32_t b1) {
    asm volatile("mma.sync.aligned.m16n8k16.row.col.f32.f16.f16.f32 "
        "{%0,%1,%2,%3}, {%4,%5,%6,%7}, {%8,%9}, {%0,%1,%2,%3};"
        : "+f"(c[0]), "+f"(c[1]), "+f"(c[2]), "+f"(c[3])
        : "r"(a[0]), "r"(a[1]), "r"(a[2]), "r"(a[3]), "r"(b0), "r"(b1));
}
__device__ __forceinline__ void ldm_x4(uint32_t* r, uint32_t addr) {
    asm volatile("ldmatrix.sync.aligned.m8n8.x4.shared.b16 {%0,%1,%2,%3}, [%4];"
        : "=r"(r[0]), "=r"(r[1]), "=r"(r[2]), "=r"(r[3]) : "r"(addr));
}
__device__ __forceinline__ uint32_t smem_u32(const void* p) {
    uint32_t a;
    asm("{ .reg .u64 t; cvta.to.shared.u64 t, %1; cvt.u32.u64 %0, t; }" : "=r"(a) : "l"(p));
    return a;
}

// ---------------- SMEM byte layout ----------------
#define W1EXT_BYTE  0                        // 160 n-rows x 48B fp16 (k16: W1|gW1 cols)
#define W3T_BYTE    7680                     // 16 n-rows x 272B fp16 (k128)  [dW3^T]
#define CF_BYTE     12032                    // 14 tiles x 16nt x 32 lanes x 16B (C frags)
#define W2F_BYTE    126720                   // W2^T fp16: 128 x 272B
#define DB2_BYTE    161536                   // 128 f
#define WT_BYTE     162048                   // 128 f (t-row of dW1)
#define GWT_BYTE    162560                   // 32 f (t-row of gW1)
#define GB1_BYTE    162688                   // 32 f
#define GB2_BYTE    162816                   // 16 f (pad 0)
#define DB3_BYTE    162880                   // 16 f (pad 0)
#define TS_BYTE     162944                   // 128 f
#define SMEM_BYTES  163456

__global__ void __launch_bounds__(TPB, 1)
sde_hmma(const float* __restrict__ z0, const float* __restrict__ activity,
         const float* __restrict__ rest, const float* __restrict__ ts,
         const float* __restrict__ noise,
         const float* __restrict__ aW1, const float* __restrict__ ab1,
         const float* __restrict__ aW2, const float* __restrict__ ab2,
         const float* __restrict__ rW1, const float* __restrict__ rb1,
         const float* __restrict__ rW2, const float* __restrict__ rb2,
         const float* __restrict__ dW1, const float* __restrict__ db1,
         const float* __restrict__ dW2, const float* __restrict__ db2,
         const float* __restrict__ dW3, const float* __restrict__ db3,
         const float* __restrict__ gW1, const float* __restrict__ gb1,
         const float* __restrict__ gW2, const float* __restrict__ gb2,
         float* __restrict__ out, int Bn, int nstep)
{
    extern __shared__ char smc[];
    const uint32_t sbase = smem_u32(smc);
    const int tid  = threadIdx.x;
    const int wid  = tid >> 5;
    const int lane = tid & 31;
    const int gid  = lane >> 2;
    const int tid4 = lane & 3;
    const int qc   = tid4 * 2;
    const int elemBase = blockIdx.x * EPC + wid * 32;   // warp owns 32 elems, 2 tiles
    const bool active  = (elemBase < Bn);

    // ================= one-time staging =================
    for (int i = tid; i < 16384; i += TPB) {
        int k = i >> 7, n = i & 127;
        *(__half*)(smc + W2F_BYTE + (uint32_t)n * 272u + (uint32_t)k * 2u) =
            __float2half_rn(dW2[i]);
    }
    if (tid < 160) {   // W1EXT rows: 0..127 drift, 128..159 diffusion
        __half* r = (__half*)(smc + W1EXT_BYTE + tid * 48);
        #pragma unroll
        for (int k = 0; k < 24; ++k) r[k] = __float2half_rn(0.0f);
        if (tid < 128) {
            #pragma unroll
            for (int j = 0; j < 10; ++j) r[j] = __float2half_rn(dW1[j * 128 + tid]);
        } else {
            #pragma unroll
            for (int j = 0; j < 10; ++j) r[j] = __float2half_rn(gW1[j * 32 + (tid - 128)]);
        }
    }
    if (tid < 16) {    // W3T: [n][k] fp16, rows 10..15 zero
        __half* r = (__half*)(smc + W3T_BYTE + tid * 272);
        for (int k = 0; k < 136; ++k) r[k] = __float2half_rn(0.0f);
        if (tid < 10)
            for (int k = 0; k < 128; ++k) r[k] = __float2half_rn(dW3[k * 10 + tid]);
    }
    if (tid < 128) {
        ((float*)(smc + WT_BYTE))[tid]  = dW1[106 * 128 + tid];
        ((float*)(smc + DB2_BYTE))[tid] = db2[tid];
    }
    if (tid < 32) {
        ((float*)(smc + GWT_BYTE))[tid] = gW1[10 * 32 + tid];
        ((float*)(smc + GB1_BYTE))[tid] = gb1[tid];
    }
    if (tid < 16) {
        ((float*)(smc + GB2_BYTE))[tid] = (tid < 10) ? gb2[tid] : 0.0f;
        ((float*)(smc + DB3_BYTE))[tid] = (tid < 10) ? db3[tid] : 0.0f;
    }
    for (int i = tid; i <= nstep && i < 128; i += TPB)
        ((float*)(smc + TS_BYTE))[i] = ts[i];

    // ---- context encoders -> C[128] scattered into CF fragment layout ----
    if (tid < EPC) {
        const int elemE = blockIdx.x * EPC + tid;
        if (elemE < Bn) {
            float actv[6], rsv[3];
            #pragma unroll
            for (int j = 0; j < 6; ++j) actv[j] = activity[elemE * 6 + j];
            #pragma unroll
            for (int j = 0; j < 3; ++j) rsv[j] = rest[elemE * 3 + j];
            float ha[32];
            #pragma unroll
            for (int o = 0; o < 32; ++o) {
                float q = __ldg(&ab1[o]);
                #pragma unroll
                for (int j = 0; j < 6; ++j) q += actv[j] * __ldg(&aW1[j * 32 + o]);
                ha[o] = fmaxf(q, 0.0f);
            }
            float av[64];
            #pragma unroll
            for (int o = 0; o < 64; ++o) {
                float q = __ldg(&ab2[o]);
                #pragma unroll
                for (int j = 0; j < 32; ++j) q += ha[j] * __ldg(&aW2[j * 64 + o]);
                av[o] = q;
            }
            float hr[16];
            #pragma unroll
            for (int o = 0; o < 16; ++o) {
                float q = __ldg(&rb1[o]);
                #pragma unroll
                for (int j = 0; j < 3; ++j) q += rsv[j] * __ldg(&rW1[j * 16 + o]);
                hr[o] = fmaxf(q, 0.0f);
            }
            float rv[32];
            #pragma unroll
            for (int o = 0; o < 32; ++o) {
                float q = __ldg(&rb2[o]);
                #pragma unroll
                for (int j = 0; j < 16; ++j) q += hr[j] * __ldg(&rW2[j * 32 + o]);
                rv[o] = q;
            }
            // tile index: warp (tid>>5), tile within warp ((tid>>4)&1)
            const int w = tid >> 5, mt = (tid >> 4) & 1, r = tid & 15;
            const uint32_t cfw = sbase + CF_BYTE + (uint32_t)(w * 2 + mt) * 8192u;
            const int laneb = (r & 7) << 2;
            const int inner = (r >= 8) ? 8 : 0;
            for (int o4 = 0; o4 < 32; ++o4) {
                float cv[4];
                #pragma unroll
                for (int c = 0; c < 4; ++c) {
                    int o = o4 * 4 + c;
                    float q = __ldg(&db1[o]);
                    #pragma unroll
                    for (int j = 0; j < 64; ++j) q += av[j] * __ldg(&dW1[(10 + j) * 128 + o]);
                    #pragma unroll
                    for (int j = 0; j < 32; ++j) q += rv[j] * __ldg(&dW1[(74 + j) * 128 + o]);
                    cv[c] = q;
                }
                const int nt = o4 >> 1;
                const int t4b = 2 * (o4 & 1);
                uint32_t a0 = cfw + (uint32_t)((nt * 32 + laneb + t4b) * 16 + inner);
                uint32_t a1a = cfw + (uint32_t)((nt * 32 + laneb + t4b + 1) * 16 + inner);
                asm volatile("st.shared.v2.f32 [%0], {%1,%2};" :: "r"(a0), "f"(cv[0]), "f"(cv[1]));
                asm volatile("st.shared.v2.f32 [%0], {%1,%2};" :: "r"(a1a), "f"(cv[2]), "f"(cv[3]));
            }
        }
    }
    __syncthreads();
    if (!active) return;

    // ---- z state in fp32 fragment registers, 2 tiles ----
    float zf0[2][4], zf1[2][4];
    #pragma unroll
    for (int mt = 0; mt < 2; ++mt) {
        const float* zb = z0 + (size_t)(elemBase + mt * 16) * 10;
        float2 a = *(const float2*)(zb + gid * 10 + qc);
        float2 b = *(const float2*)(zb + (gid + 8) * 10 + qc);
        zf0[mt][0] = a.x; zf0[mt][1] = a.y; zf0[mt][2] = b.x; zf0[mt][3] = b.y;
        zf1[mt][0] = zf1[mt][1] = zf1[mt][2] = zf1[mt][3] = 0.0f;
        if (tid4 == 0) {
            float2 c = *(const float2*)(zb + gid * 10 + 8);
            float2 d = *(const float2*)(zb + (gid + 8) * 10 + 8);
            zf1[mt][0] = c.x; zf1[mt][1] = c.y; zf1[mt][2] = d.x; zf1[mt][3] = d.y;
        }
        float* ob = out + (size_t)(elemBase + mt * 16) * 10;
        *(float2*)(ob + gid * 10 + qc)       = make_float2(zf0[mt][0], zf0[mt][1]);
        *(float2*)(ob + (gid + 8) * 10 + qc) = make_float2(zf0[mt][2], zf0[mt][3]);
        if (tid4 == 0) {
            *(float2*)(ob + gid * 10 + 8)       = make_float2(zf1[mt][0], zf1[mt][1]);
            *(float2*)(ob + (gid + 8) * 10 + 8) = make_float2(zf1[mt][2], zf1[mt][3]);
        }
    }

    // ---- gW2 B-fragments (registers, fixed) ----
    uint32_t gB[2][2][2];
    #pragma unroll
    for (int kt = 0; kt < 2; ++kt)
        #pragma unroll
        for (int nt = 0; nt < 2; ++nt) {
            const int n = nt * 8 + gid;
            float w00 = 0.f, w01 = 0.f, w10 = 0.f, w11 = 0.f;
            if (n < 10) {
                w00 = gW2[(16 * kt + 2 * tid4)     * 10 + n];
                w01 = gW2[(16 * kt + 2 * tid4 + 1) * 10 + n];
                w10 = gW2[(16 * kt + 2 * tid4 + 8) * 10 + n];
                w11 = gW2[(16 * kt + 2 * tid4 + 9) * 10 + n];
            }
            gB[kt][nt][0] = f16x2_of(w00, w01);
            gB[kt][nt][1] = f16x2_of(w10, w11);
        }
    float d3r[4], ga[4];
    {
        const float* d3 = (const float*)(smc + DB3_BYTE);
        const float* g2 = (const float*)(smc + GB2_BYTE);
        d3r[0] = d3[qc]; d3r[1] = d3[qc + 1]; d3r[2] = d3[8 + qc]; d3r[3] = d3[9 + qc];
        ga[0]  = g2[qc]; ga[1]  = g2[qc + 1]; ga[2]  = g2[8 + qc]; ga[3]  = g2[9 + qc];
    }

    // precomputed addresses
    const uint32_t w1L   = sbase + W1EXT_BYTE + (uint32_t)(lane & 7) * 48u
                         + (((uint32_t)lane >> 3) & 1u) * 16u + ((uint32_t)lane >> 4) * 384u;
    const uint32_t w3tL  = sbase + W3T_BYTE + (uint32_t)(lane & 7) * 272u
                         + ((uint32_t)lane >> 3) * 16u;
    const uint32_t bLdmLane = (uint32_t)(lane & 7) * 272u + ((uint32_t)lane >> 3) * 16u;
    const uint32_t cfW   = sbase + CF_BYTE + (uint32_t)(wid * 2) * 8192u + (uint32_t)lane * 16u;
    const float* tsf = (const float*)(smc + TS_BYTE);

    // ================= SDE integration (2 M-tiles per warp, reg-resident) =================
    for (int s = 0; s < nstep; ++s) {
        const float t  = tsf[s];
        const float dt = tsf[s + 1] - t;
        const float sq = sqrtf(dt);

        // ---- prefetch noise fragments for both tiles ----
        float2 e00[2], e01[2], e10[2], e11[2];
        #pragma unroll
        for (int mt = 0; mt < 2; ++mt) {
            const float* nb = noise + ((size_t)s * Bn + elemBase + mt * 16) * 10;
            e00[mt] = *(const float2*)(nb + gid * 10 + qc);
            e01[mt] = *(const float2*)(nb + (gid + 8) * 10 + qc);
            e10[mt] = make_float2(0.f, 0.f); e11[mt] = make_float2(0.f, 0.f);
            if (tid4 == 0) {
                e10[mt] = *(const float2*)(nb + gid * 10 + 8);
                e11[mt] = *(const float2*)(nb + (gid + 8) * 10 + 8);
            }
        }

        // ---- za A-fragments from state registers ----
        uint32_t za[2][4];
        #pragma unroll
        for (int mt = 0; mt < 2; ++mt) {
            za[mt][0] = f16x2_of(zf0[mt][0], zf0[mt][1]);
            za[mt][1] = f16x2_of(zf0[mt][2], zf0[mt][3]);
            za[mt][2] = f16x2_of(zf1[mt][0], zf1[mt][1]);
            za[mt][3] = f16x2_of(zf1[mt][2], zf1[mt][3]);
        }

        // ---- GEMM1 drift: per kt-group immediate accumulate->tanh->pack (low reg peak) ----
        uint32_t af[2][8][4];
        #pragma unroll
        for (int hd = 0; hd < 2; ++hd) {
            #pragma unroll
            for (int i = 0; i < 4; ++i) {
                uint32_t bw[4];
                ldm_x4(bw, w1L + (uint32_t)(8 * hd + 2 * i) * 384u);
                #pragma unroll
                for (int mt = 0; mt < 2; ++mt) {
                    float a1p[2][4];
                    #pragma unroll
                    for (int p = 0; p < 2; ++p) {
                        const int gnt = 8 * hd + 2 * i + p;
                        float4 cf;
                        asm volatile("ld.shared.v4.f32 {%0,%1,%2,%3}, [%4];"
                            : "=f"(cf.x), "=f"(cf.y), "=f"(cf.z), "=f"(cf.w)
                            : "r"(cfW + (uint32_t)mt * 8192u + (uint32_t)gnt * 512u));
                        float2 w2 = *(const float2*)(smc + WT_BYTE + (gnt * 8 + qc) * 4);
                        a1p[p][0] = fmaf(t, w2.x, cf.x);
                        a1p[p][1] = fmaf(t, w2.y, cf.y);
                        a1p[p][2] = fmaf(t, w2.x, cf.z);
                        a1p[p][3] = fmaf(t, w2.y, cf.w);
                    }
                    mma_f16(a1p[0], za[mt], bw[0], bw[1]);
                    mma_f16(a1p[1], za[mt], bw[2], bw[3]);
                    af[mt][4 * hd + i][0] = tanh2(f16x2_of(a1p[0][0], a1p[0][1]));
                    af[mt][4 * hd + i][1] = tanh2(f16x2_of(a1p[0][2], a1p[0][3]));
                    af[mt][4 * hd + i][2] = tanh2(f16x2_of(a1p[1][0], a1p[1][1]));
                    af[mt][4 * hd + i][3] = tanh2(f16x2_of(a1p[1][2], a1p[1][3]));
                }
            }
        }

        // ---- diffusion: GEMM-ext + softplus + GEMM-g; fold g-term into zf now ----
        {
            float ag[2][4][4];
            const float* gb1f = (const float*)(smc + GB1_BYTE);
            const float* gwtf = (const float*)(smc + GWT_BYTE);
            #pragma unroll
            for (int nt = 0; nt < 4; ++nt) {
                const int c0 = nt * 8 + qc;
                float b0 = fmaf(t, gwtf[c0],     gb1f[c0]);
                float b1 = fmaf(t, gwtf[c0 + 1], gb1f[c0 + 1]);
                #pragma unroll
                for (int mt = 0; mt < 2; ++mt) {
                    ag[mt][nt][0] = b0; ag[mt][nt][1] = b1;
                    ag[mt][nt][2] = b0; ag[mt][nt][3] = b1;
                }
            }
            #pragma unroll
            for (int i = 0; i < 2; ++i) {
                uint32_t bw[4];
                ldm_x4(bw, w1L + (uint32_t)(128 + 16 * i) * 48u);
                #pragma unroll
                for (int mt = 0; mt < 2; ++mt) {
                    mma_f16(ag[mt][2 * i],     za[mt], bw[0], bw[1]);
                    mma_f16(ag[mt][2 * i + 1], za[mt], bw[2], bw[3]);
                }
            }
            #pragma unroll
            for (int mt = 0; mt < 2; ++mt) {
                uint32_t qf[2][4];
                #pragma unroll
                for (int kt = 0; kt < 2; ++kt) {
                    qf[kt][0] = f16x2_of(softplus_(ag[mt][2 * kt][0]),     softplus_(ag[mt][2 * kt][1]));
                    qf[kt][1] = f16x2_of(softplus_(ag[mt][2 * kt][2]),     softplus_(ag[mt][2 * kt][3]));
                    qf[kt][2] = f16x2_of(softplus_(ag[mt][2 * kt + 1][0]), softplus_(ag[mt][2 * kt + 1][1]));
                    qf[kt][3] = f16x2_of(softplus_(ag[mt][2 * kt + 1][2]), softplus_(ag[mt][2 * kt + 1][3]));
                }
                float accg[2][4];
                accg[0][0] = ga[0]; accg[0][1] = ga[1]; accg[0][2] = ga[0]; accg[0][3] = ga[1];
                accg[1][0] = ga[2]; accg[1][1] = ga[3]; accg[1][2] = ga[2]; accg[1][3] = ga[3];
                #pragma unroll
                for (int kt = 0; kt < 2; ++kt) {
                    mma_f16(accg[0], qf[kt], gB[kt][0][0], gB[kt][0][1]);
                    mma_f16(accg[1], qf[kt], gB[kt][1][0], gB[kt][1][1]);
                }
                // fold diffusion term into state now (EM update is additive)
                zf0[mt][0] += accg[0][0] * sq * e00[mt].x;
                zf0[mt][1] += accg[0][1] * sq * e00[mt].y;
                zf0[mt][2] += accg[0][2] * sq * e01[mt].x;
                zf0[mt][3] += accg[0][3] * sq * e01[mt].y;
                zf1[mt][0] += accg[1][0] * sq * e10[mt].x;
                zf1[mt][1] += accg[1][1] * sq * e10[mt].y;
                zf1[mt][2] += accg[1][2] * sq * e11[mt].x;
                zf1[mt][3] += accg[1][3] * sq * e11[mt].y;
            }
        }

        // ---- GEMM2 (h2) fused with GEMM3 (dz), shared B-ldm for both tiles ----
        float acc3[2][2][4];
        #pragma unroll
        for (int mt = 0; mt < 2; ++mt) {
            acc3[mt][0][0] = d3r[0]; acc3[mt][0][1] = d3r[1];
            acc3[mt][0][2] = d3r[0]; acc3[mt][0][3] = d3r[1];
            acc3[mt][1][0] = d3r[2]; acc3[mt][1][1] = d3r[3];
            acc3[mt][1][2] = d3r[2]; acc3[mt][1][3] = d3r[3];
        }
        #pragma unroll
        for (int ng = 0; ng < 4; ++ng) {
            float acc[2][4][4];
            #pragma unroll
            for (int ni = 0; ni < 4; ++ni) {
                float2 d2 = *(const float2*)(smc + DB2_BYTE + ((ng * 4 + ni) * 8 + qc) * 4);
                #pragma unroll
                for (int mt = 0; mt < 2; ++mt) {
                    acc[mt][ni][0] = d2.x; acc[mt][ni][1] = d2.y;
                    acc[mt][ni][2] = d2.x; acc[mt][ni][3] = d2.y;
                }
            }
            #pragma unroll
            for (int ni = 0; ni < 4; ++ni) {
                const uint32_t brow = sbase + W2F_BYTE + bLdmLane
                                    + (uint32_t)((ng * 4 + ni) * 8) * 272u;
                #pragma unroll
                for (int ktp = 0; ktp < 4; ++ktp) {
                    uint32_t r[4];
                    ldm_x4(r, brow + (uint32_t)ktp * 64u);
                    #pragma unroll
                    for (int mt = 0; mt < 2; ++mt) {
                        mma_f16(acc[mt][ni], af[mt][2 * ktp],     r[0], r[1]);
                        mma_f16(acc[mt][ni], af[mt][2 * ktp + 1], r[2], r[3]);
                    }
                }
            }
            uint32_t r3a[4], r3b[4];
            ldm_x4(r3a, w3tL + (uint32_t)ng * 64u);
            ldm_x4(r3b, w3tL + 8 * 272u + (uint32_t)ng * 64u);
            #pragma unroll
            for (int mt = 0; mt < 2; ++mt)
                #pragma unroll
                for (int p = 0; p < 2; ++p) {
                    uint32_t a3[4];
                    a3[0] = tanh2(f16x2_of(acc[mt][2 * p][0],     acc[mt][2 * p][1]));
                    a3[1] = tanh2(f16x2_of(acc[mt][2 * p][2],     acc[mt][2 * p][3]));
                    a3[2] = tanh2(f16x2_of(acc[mt][2 * p + 1][0], acc[mt][2 * p + 1][1]));
                    a3[3] = tanh2(f16x2_of(acc[mt][2 * p + 1][2], acc[mt][2 * p + 1][3]));
                    mma_f16(acc3[mt][0], a3, r3a[2 * p], r3a[2 * p + 1]);
                    mma_f16(acc3[mt][1], a3, r3b[2 * p], r3b[2 * p + 1]);
                }
        }

        // ---- drift term + store (g-term already folded) ----
        #pragma unroll
        for (int mt = 0; mt < 2; ++mt) {
            zf0[mt][0] += acc3[mt][0][0] * dt;
            zf0[mt][1] += acc3[mt][0][1] * dt;
            zf0[mt][2] += acc3[mt][0][2] * dt;
            zf0[mt][3] += acc3[mt][0][3] * dt;
            zf1[mt][0] += acc3[mt][1][0] * dt;
            zf1[mt][1] += acc3[mt][1][1] * dt;
            zf1[mt][2] += acc3[mt][1][2] * dt;
            zf1[mt][3] += acc3[mt][1][3] * dt;

            float* ob = out + ((size_t)(s + 1) * Bn + elemBase + mt * 16) * 10;
            *(float2*)(ob + gid * 10 + qc)       = make_float2(zf0[mt][0], zf0[mt][1]);
            *(float2*)(ob + (gid + 8) * 10 + qc) = make_float2(zf0[mt][2], zf0[mt][3]);
            if (tid4 == 0) {
                *(float2*)(ob + gid * 10 + 8)       = make_float2(zf1[mt][0], zf1[mt][1]);
                *(float2*)(ob + (gid + 8) * 10 + 8) = make_float2(zf1[mt][2], zf1[mt][3]);
            }
        }
    }
}

extern "C" void kernel_launch(void* const* d_in, const int* in_sizes, int n_in,
                              void* d_out, int out_size) {
    const float* z0       = (const float*)d_in[0];
    const float* activity = (const float*)d_in[1];
    const float* rest     = (const float*)d_in[2];
    const float* ts       = (const float*)d_in[3];
    const float* noise    = (const float*)d_in[4];
    const float* aW1 = (const float*)d_in[5];
    const float* ab1 = (const float*)d_in[6];
    const float* aW2 = (const float*)d_in[7];
    const float* ab2 = (const float*)d_in[8];
    const float* rW1 = (const float*)d_in[9];
    const float* rb1 = (const float*)d_in[10];
    const float* rW2 = (const float*)d_in[11];
    const float* rb2 = (const float*)d_in[12];
    const float* dW1 = (const float*)d_in[13];
    const float* db1 = (const float*)d_in[14];
    const float* dW2 = (const float*)d_in[15];
    const float* db2 = (const float*)d_in[16];
    const float* dW3 = (const float*)d_in[17];
    const float* db3 = (const float*)d_in[18];
    const float* gW1 = (const float*)d_in[19];
    const float* gb1 = (const float*)d_in[20];
    const float* gW2 = (const float*)d_in[21];
    const float* gb2 = (const float*)d_in[22];

    int B     = in_sizes[0] / 10;
    int nstep = in_sizes[3] - 1;

    cudaFuncSetAttribute(sde_hmma, cudaFuncAttributeMaxDynamicSharedMemorySize,
                         SMEM_BYTES);
    int grid = (B + EPC - 1) / EPC;
    sde_hmma<<<grid, TPB, SMEM_BYTES>>>(
        z0, activity, rest, ts, noise,
        aW1, ab1, aW2, ab2, rW1, rb1, rW2, rb2,
        dW1, db1, dW2, db2, dW3, db3,
        gW1, gb1, gW2, gb2,
        (float*)d_out, B, nstep);
}